// round 1
// baseline (speedup 1.0000x reference)
#include <cuda_runtime.h>
#include <cstdint>
#include <math.h>

// Problem constants
#define B_    2048
#define HW    256
#define SE_   8
#define CE_   16
#define ESZ_  512
#define NZ_   512

// ---------------- scratch (static device globals; no allocation) ----------------
__device__ float g_table[14 * 8];
__device__ float g_zn[NZ_ * ESZ_];
__device__ float g_se[(size_t)B_ * CE_ * HW];
__device__ float g_de[(size_t)B_ * CE_ * HW];
__device__ float g_act[2 * (size_t)B_ * 8192];
__device__ float g_embed[2 * (size_t)B_ * ESZ_];
__device__ float g_scores[(size_t)B_ * NZ_];
__device__ int   g_zind[B_];
__device__ float g_escale;

// ---------------- prep: normalize z rows, embedding table, exp(scale) ----------------
__global__ void prep_kernel(const float* __restrict__ state_embed,
                            const float* __restrict__ zv,
                            const float* __restrict__ scale)
{
    int t = threadIdx.x;
    int blk = blockIdx.x;
    if (blk < NZ_) {
        __shared__ float red[128];
        const float* zr = zv + (size_t)blk * ESZ_;
        float v[4];
        float s = 0.f;
        #pragma unroll
        for (int i = 0; i < 4; i++) { v[i] = zr[t + i * 128]; s += v[i] * v[i]; }
        red[t] = s; __syncthreads();
        for (int off = 64; off > 0; off >>= 1) {
            if (t < off) red[t] += red[t + off];
            __syncthreads();
        }
        float inv = 1.0f / sqrtf(red[0]);   // eps = 0 for z vectors
        float* o = g_zn + (size_t)blk * ESZ_;
        #pragma unroll
        for (int i = 0; i < 4; i++) o[t + i * 128] = v[i] * inv;
    } else {
        if (t < 14) {
            float s = 0.f;
            #pragma unroll
            for (int j = 0; j < 8; j++) { float x = state_embed[t * 8 + j]; s += x * x; }
            float d = fmaxf(sqrtf(s), 1.0f);
            #pragma unroll
            for (int j = 0; j < 8; j++) g_table[t * 8 + j] = state_embed[t * 8 + j] / d;
        }
        if (t == 0) g_escale = expf(scale[0]);
    }
}

// ---------------- embed gather + 3x3 conv (8ch -> 16ch), fused for s and (s'-s) ----------------
__global__ __launch_bounds__(256) void embed_kernel(
    const int* __restrict__ s, const int* __restrict__ sp,
    const float* __restrict__ cw, const float* __restrict__ cb)
{
    __shared__ float tab[14 * 8];
    __shared__ float w[CE_ * SE_ * 9];
    __shared__ float bias[CE_];
    __shared__ float xs[SE_ * 324];   // padded 18x18 per channel
    __shared__ float xd[SE_ * 324];

    int tid = threadIdx.x;
    int b = blockIdx.x;

    if (tid < 112) tab[tid] = g_table[tid];
    for (int i = tid; i < CE_ * SE_ * 9; i += 256) w[i] = cw[i];
    if (tid < CE_) bias[tid] = cb[tid];
    for (int i = tid; i < SE_ * 324; i += 256) { xs[i] = 0.f; xd[i] = 0.f; }
    __syncthreads();

    int py0 = tid >> 4, px0 = tid & 15;
    int sv  = s[(size_t)b * HW + tid];
    int spv = sp[(size_t)b * HW + tid];
    #pragma unroll
    for (int ic = 0; ic < SE_; ic++) {
        float a = tab[sv * 8 + ic];
        float c = tab[spv * 8 + ic];
        int o = ic * 324 + (py0 + 1) * 18 + px0 + 1;
        xs[o] = a;
        xd[o] = c - a;           // conv(x'-x) == sp_e - s_e (bias cancels)
    }
    __syncthreads();

    int ocg = tid >> 6;          // 4 groups of 4 output channels
    int y   = (tid >> 2) & 15;
    int xg  = (tid & 3) * 4;

    float as[4][4] = {}, ad[4][4] = {};
    #pragma unroll
    for (int ic = 0; ic < SE_; ic++) {
        const float* ps = xs + ic * 324 + y * 18 + xg;
        const float* pd = xd + ic * 324 + y * 18 + xg;
        #pragma unroll
        for (int dy = 0; dy < 3; dy++)
        #pragma unroll
        for (int dx = 0; dx < 3; dx++) {
            int off = dy * 18 + dx;
            float s0 = ps[off], s1 = ps[off + 1], s2 = ps[off + 2], s3 = ps[off + 3];
            float d0 = pd[off], d1 = pd[off + 1], d2 = pd[off + 2], d3 = pd[off + 3];
            #pragma unroll
            for (int j = 0; j < 4; j++) {
                float wv = w[(ocg * 4 + j) * 72 + ic * 9 + dy * 3 + dx];
                as[j][0] += wv * s0; as[j][1] += wv * s1; as[j][2] += wv * s2; as[j][3] += wv * s3;
                ad[j][0] += wv * d0; ad[j][1] += wv * d1; ad[j][2] += wv * d2; ad[j][3] += wv * d3;
            }
        }
    }
    #pragma unroll
    for (int j = 0; j < 4; j++) {
        int oc = ocg * 4 + j;
        float bb = bias[oc];
        size_t o = ((size_t)b * CE_ + oc) * HW + y * 16 + xg;
        float4 v1 = make_float4(as[j][0] + bb, as[j][1] + bb, as[j][2] + bb, as[j][3] + bb);
        float4 v2 = make_float4(ad[j][0], ad[j][1], ad[j][2], ad[j][3]);
        *(float4*)(g_se + o) = v1;
        *(float4*)(g_de + o) = v2;
    }
}

// ---------------- fused tower: conv1(16->16)+relu, conv2(16->32)+relu ----------------
#define TOWER_SMEM_FLOATS (5184 * 2 + 2304 + 4608 + 16 + 32)
#define TOWER_SMEM_BYTES  (TOWER_SMEM_FLOATS * 4)

__global__ __launch_bounds__(256) void tower_kernel(
    const float* __restrict__ w1a, const float* __restrict__ b1a,
    const float* __restrict__ w2a, const float* __restrict__ b2a,
    const float* __restrict__ w1b, const float* __restrict__ b1b,
    const float* __restrict__ w2b, const float* __restrict__ b2b)
{
    extern __shared__ float sm[];
    float* pin = sm;                 // 16 * 324
    float* mid = sm + 5184;          // 16 * 324
    float* w1  = sm + 10368;         // 16*16*9
    float* w2  = sm + 12672;         // 32*16*9
    float* bb1 = sm + 17280;         // 16
    float* bb2 = sm + 17296;         // 32

    int tid = threadIdx.x;
    int b   = blockIdx.x;
    int tw  = blockIdx.y;

    const float* in  = tw ? g_de : g_se;
    const float* w1g = tw ? w1b : w1a;
    const float* b1g = tw ? b1b : b1a;
    const float* w2g = tw ? w2b : w2a;
    const float* b2g = tw ? b2b : b2a;

    for (int i = tid; i < 10368; i += 256) sm[i] = 0.f;    // zero pads of pin & mid
    for (int i = tid; i < 2304; i += 256) w1[i] = w1g[i];
    for (int i = tid; i < 4608; i += 256) w2[i] = w2g[i];
    if (tid < 16) bb1[tid] = b1g[tid];
    if (tid < 32) bb2[tid] = b2g[tid];
    __syncthreads();

    int py0 = tid >> 4, px0 = tid & 15;
    #pragma unroll
    for (int c = 0; c < 16; c++)
        pin[c * 324 + (py0 + 1) * 18 + px0 + 1] = in[((size_t)b * 16 + c) * HW + tid];
    __syncthreads();

    int ocg = tid >> 6;
    int y   = (tid >> 2) & 15;
    int xg  = (tid & 3) * 4;

    // conv1: 16 -> 16
    {
        float acc[4][4] = {};
        #pragma unroll
        for (int ic = 0; ic < 16; ic++) {
            const float* pi = pin + ic * 324 + y * 18 + xg;
            #pragma unroll
            for (int dy = 0; dy < 3; dy++)
            #pragma unroll
            for (int dx = 0; dx < 3; dx++) {
                int off = dy * 18 + dx;
                float v0 = pi[off], v1 = pi[off + 1], v2 = pi[off + 2], v3 = pi[off + 3];
                #pragma unroll
                for (int j = 0; j < 4; j++) {
                    float wv = w1[(ocg * 4 + j) * 144 + ic * 9 + dy * 3 + dx];
                    acc[j][0] += wv * v0; acc[j][1] += wv * v1;
                    acc[j][2] += wv * v2; acc[j][3] += wv * v3;
                }
            }
        }
        #pragma unroll
        for (int j = 0; j < 4; j++) {
            int oc = ocg * 4 + j;
            float bbv = bb1[oc];
            float* mp = mid + oc * 324 + (y + 1) * 18 + xg + 1;
            mp[0] = fmaxf(acc[j][0] + bbv, 0.f);
            mp[1] = fmaxf(acc[j][1] + bbv, 0.f);
            mp[2] = fmaxf(acc[j][2] + bbv, 0.f);
            mp[3] = fmaxf(acc[j][3] + bbv, 0.f);
        }
    }
    __syncthreads();

    // conv2: 16 -> 32
    {
        float a2[8][4] = {};
        #pragma unroll 2
        for (int ic = 0; ic < 16; ic++) {
            const float* pi = mid + ic * 324 + y * 18 + xg;
            #pragma unroll
            for (int dy = 0; dy < 3; dy++)
            #pragma unroll
            for (int dx = 0; dx < 3; dx++) {
                int off = dy * 18 + dx;
                float v0 = pi[off], v1 = pi[off + 1], v2 = pi[off + 2], v3 = pi[off + 3];
                #pragma unroll
                for (int j = 0; j < 8; j++) {
                    float wv = w2[(ocg * 8 + j) * 144 + ic * 9 + dy * 3 + dx];
                    a2[j][0] += wv * v0; a2[j][1] += wv * v1;
                    a2[j][2] += wv * v2; a2[j][3] += wv * v3;
                }
            }
        }
        float* act = g_act + (size_t)tw * B_ * 8192;
        #pragma unroll
        for (int j = 0; j < 8; j++) {
            int oc = ocg * 8 + j;
            float bbv = bb2[oc];
            float4 v = make_float4(fmaxf(a2[j][0] + bbv, 0.f), fmaxf(a2[j][1] + bbv, 0.f),
                                   fmaxf(a2[j][2] + bbv, 0.f), fmaxf(a2[j][3] + bbv, 0.f));
            *(float4*)(act + (size_t)b * 8192 + oc * HW + y * 16 + xg) = v;
        }
    }
}

// ---------------- generic SGEMM: C[M,N] = alpha * A[M,K] . B[N,K]^T (+bias), optional B-row gather ----------------
template<bool GATHER, bool SCALE, bool BIAS>
__global__ __launch_bounds__(256) void sgemm_kernel(
    const float* __restrict__ A, const float* __restrict__ Bm,
    const float* __restrict__ bias, float* __restrict__ C,
    int M, int N, int K)
{
    __shared__ float As[2][8][128];
    __shared__ float Bs[2][8][128];

    int tid = threadIdx.x;
    int tx = tid & 15, ty = tid >> 4;
    int bm = blockIdx.y * 128, bn = blockIdx.x * 128;

    int lr = tid >> 1;             // 0..127
    int lc = (tid & 1) * 4;        // 0 or 4
    const float* Ald = A + (size_t)(bm + lr) * K + lc;
    int brw = GATHER ? g_zind[bn + lr] : (bn + lr);
    const float* Bld = Bm + (size_t)brw * K + lc;

    float4 a4 = *(const float4*)Ald;
    float4 b4 = *(const float4*)Bld;
    As[0][lc + 0][lr] = a4.x; As[0][lc + 1][lr] = a4.y;
    As[0][lc + 2][lr] = a4.z; As[0][lc + 3][lr] = a4.w;
    Bs[0][lc + 0][lr] = b4.x; Bs[0][lc + 1][lr] = b4.y;
    Bs[0][lc + 2][lr] = b4.z; Bs[0][lc + 3][lr] = b4.w;
    __syncthreads();

    float acc[8][8] = {};
    int nk = K >> 3;
    for (int kt = 0; kt < nk; kt++) {
        int buf = kt & 1;
        if (kt + 1 < nk) {
            a4 = *(const float4*)(Ald + (size_t)(kt + 1) * 8);
            b4 = *(const float4*)(Bld + (size_t)(kt + 1) * 8);
        }
        #pragma unroll
        for (int kk = 0; kk < 8; kk++) {
            float ar[8], brr[8];
            *(float4*)&ar[0]  = *(const float4*)&As[buf][kk][ty * 8];
            *(float4*)&ar[4]  = *(const float4*)&As[buf][kk][ty * 8 + 4];
            *(float4*)&brr[0] = *(const float4*)&Bs[buf][kk][tx * 8];
            *(float4*)&brr[4] = *(const float4*)&Bs[buf][kk][tx * 8 + 4];
            #pragma unroll
            for (int i = 0; i < 8; i++)
                #pragma unroll
                for (int j = 0; j < 8; j++)
                    acc[i][j] += ar[i] * brr[j];
        }
        if (kt + 1 < nk) {
            int nb = buf ^ 1;
            As[nb][lc + 0][lr] = a4.x; As[nb][lc + 1][lr] = a4.y;
            As[nb][lc + 2][lr] = a4.z; As[nb][lc + 3][lr] = a4.w;
            Bs[nb][lc + 0][lr] = b4.x; Bs[nb][lc + 1][lr] = b4.y;
            Bs[nb][lc + 2][lr] = b4.z; Bs[nb][lc + 3][lr] = b4.w;
        }
        __syncthreads();
    }

    float alpha = SCALE ? g_escale : 1.0f;
    float bz[8];
    #pragma unroll
    for (int j = 0; j < 8; j++) bz[j] = BIAS ? bias[bn + tx * 8 + j] : 0.0f;
    #pragma unroll
    for (int i = 0; i < 8; i++) {
        float* cp = C + (size_t)(bm + ty * 8 + i) * N + bn + tx * 8;
        float4 o0, o1;
        o0.x = acc[i][0] * alpha + bz[0]; o0.y = acc[i][1] * alpha + bz[1];
        o0.z = acc[i][2] * alpha + bz[2]; o0.w = acc[i][3] * alpha + bz[3];
        o1.x = acc[i][4] * alpha + bz[4]; o1.y = acc[i][5] * alpha + bz[5];
        o1.z = acc[i][6] * alpha + bz[6]; o1.w = acc[i][7] * alpha + bz[7];
        *(float4*)cp = o0;
        *(float4*)(cp + 4) = o1;
    }
}

// ---------------- row L2-normalization with eps (both embeds, 4096 rows) ----------------
__global__ void normalize_kernel()
{
    int row = blockIdx.x;
    float* e = g_embed + (size_t)row * ESZ_;
    int t = threadIdx.x;
    __shared__ float red[128];
    float v[4]; float s = 0.f;
    #pragma unroll
    for (int i = 0; i < 4; i++) { v[i] = e[t + i * 128]; s += v[i] * v[i]; }
    red[t] = s; __syncthreads();
    for (int off = 64; off > 0; off >>= 1) {
        if (t < off) red[t] += red[t + off];
        __syncthreads();
    }
    float inv = 1.0f / (sqrtf(red[0]) + 1e-4f);
    #pragma unroll
    for (int i = 0; i < 4; i++) e[t + i * 128] = v[i] * inv;
}

// ---------------- argmax over scores rows (first-max tie-break, matches jnp.argmax) ----------------
__global__ void argmax_kernel()
{
    int r = blockIdx.x, t = threadIdx.x;
    const float* sr = g_scores + (size_t)r * NZ_;
    __shared__ float sv[256];
    __shared__ int   si[256];
    float v0 = sr[t], v1 = sr[t + 256];
    float bv = v0; int bi = t;
    if (v1 > bv) { bv = v1; bi = t + 256; }
    sv[t] = bv; si[t] = bi; __syncthreads();
    for (int off = 128; off > 0; off >>= 1) {
        if (t < off) {
            float ov = sv[t + off]; int oi = si[t + off];
            if (ov > sv[t] || (ov == sv[t] && oi < si[t])) { sv[t] = ov; si[t] = oi; }
        }
        __syncthreads();
    }
    if (t == 0) g_zind[r] = si[0];
}

// ---------------- launch ----------------
extern "C" void kernel_launch(void* const* d_in, const int* in_sizes, int n_in,
                              void* d_out, int out_size)
{
    (void)in_sizes; (void)n_in; (void)out_size;
    const int*   s       = (const int*)d_in[0];
    const int*   sp      = (const int*)d_in[1];
    const float* state_e = (const float*)d_in[2];
    const float* cew     = (const float*)d_in[3];
    const float* ceb     = (const float*)d_in[4];
    const float* p1c1w   = (const float*)d_in[5];
    const float* p1c1b   = (const float*)d_in[6];
    const float* p1c2w   = (const float*)d_in[7];
    const float* p1c2b   = (const float*)d_in[8];
    const float* p1lw    = (const float*)d_in[9];
    const float* p1lb    = (const float*)d_in[10];
    const float* p2c1w   = (const float*)d_in[11];
    const float* p2c1b   = (const float*)d_in[12];
    const float* p2c2w   = (const float*)d_in[13];
    const float* p2c2b   = (const float*)d_in[14];
    const float* p2lw    = (const float*)d_in[15];
    const float* p2lb    = (const float*)d_in[16];
    const float* zv      = (const float*)d_in[17];
    const float* scale   = (const float*)d_in[18];

    void *pa, *pe, *pz, *ps;
    cudaGetSymbolAddress(&pa, g_act);
    cudaGetSymbolAddress(&pe, g_embed);
    cudaGetSymbolAddress(&pz, g_zn);
    cudaGetSymbolAddress(&ps, g_scores);
    float* act    = (float*)pa;
    float* emb    = (float*)pe;
    float* zn     = (float*)pz;
    float* scores = (float*)ps;

    cudaFuncSetAttribute(tower_kernel,
                         cudaFuncAttributeMaxDynamicSharedMemorySize, TOWER_SMEM_BYTES);

    prep_kernel<<<513, 128>>>(state_e, zv, scale);
    embed_kernel<<<B_, 256>>>(s, sp, cew, ceb);
    tower_kernel<<<dim3(B_, 2), 256, TOWER_SMEM_BYTES>>>(
        p1c1w, p1c1b, p1c2w, p1c2b, p2c1w, p2c1b, p2c2w, p2c2b);

    // linear 8192 -> 512 for each tower (with bias)
    sgemm_kernel<false, false, true><<<dim3(4, 16), 256>>>(
        act, p1lw, p1lb, emb, B_, ESZ_, 8192);
    sgemm_kernel<false, false, true><<<dim3(4, 16), 256>>>(
        act + (size_t)B_ * 8192, p2lw, p2lb, emb + (size_t)B_ * ESZ_, B_, ESZ_, 8192);

    normalize_kernel<<<2 * B_, 128>>>();

    // scores = embed2 . zn^T
    sgemm_kernel<false, false, false><<<dim3(4, 16), 256>>>(
        emb + (size_t)B_ * ESZ_, zn, nullptr, scores, B_, NZ_, ESZ_);

    argmax_kernel<<<B_, 256>>>();

    // out = exp(scale) * embed1 . zn[z_inds]^T
    sgemm_kernel<true, true, false><<<dim3(16, 16), 256>>>(
        emb, zn, nullptr, (float*)d_out, B_, B_, ESZ_);
}

// round 2
// speedup vs baseline: 1.8303x; 1.8303x over previous
#include <cuda_runtime.h>
#include <cstdint>
#include <math.h>

// Problem constants
#define B_    2048
#define HW    256
#define SE_   8
#define CE_   16
#define ESZ_  512
#define NZ_   512

// ---------------- scratch (static device globals; no allocation) ----------------
__device__ float g_table[14 * 8];
__device__ float g_zn[NZ_ * ESZ_];
__device__ float g_se[(size_t)B_ * CE_ * HW];
__device__ float g_de[(size_t)B_ * CE_ * HW];
__device__ float g_act[2 * (size_t)B_ * 8192];
__device__ float g_part[4 * (size_t)B_ * ESZ_];
__device__ float g_embed[2 * (size_t)B_ * ESZ_];
__device__ float g_scores[(size_t)B_ * NZ_];
__device__ int   g_zind[B_];
__device__ float g_escale;

// ---------------- prep: normalize z rows, embedding table, exp(scale) ----------------
__global__ void prep_kernel(const float* __restrict__ state_embed,
                            const float* __restrict__ zv,
                            const float* __restrict__ scale)
{
    int t = threadIdx.x;
    int blk = blockIdx.x;
    if (blk < NZ_) {
        __shared__ float red[128];
        const float* zr = zv + (size_t)blk * ESZ_;
        float v[4];
        float s = 0.f;
        #pragma unroll
        for (int i = 0; i < 4; i++) { v[i] = zr[t + i * 128]; s += v[i] * v[i]; }
        red[t] = s; __syncthreads();
        for (int off = 64; off > 0; off >>= 1) {
            if (t < off) red[t] += red[t + off];
            __syncthreads();
        }
        float inv = 1.0f / sqrtf(red[0]);   // eps = 0 for z vectors
        float* o = g_zn + (size_t)blk * ESZ_;
        #pragma unroll
        for (int i = 0; i < 4; i++) o[t + i * 128] = v[i] * inv;
    } else {
        if (t < 14) {
            float s = 0.f;
            #pragma unroll
            for (int j = 0; j < 8; j++) { float x = state_embed[t * 8 + j]; s += x * x; }
            float d = fmaxf(sqrtf(s), 1.0f);
            #pragma unroll
            for (int j = 0; j < 8; j++) g_table[t * 8 + j] = state_embed[t * 8 + j] / d;
        }
        if (t == 0) g_escale = expf(scale[0]);
    }
}

// ---------------- embed gather + 3x3 conv (8ch -> 16ch), fused for s and (s'-s) ----------------
__global__ __launch_bounds__(256) void embed_kernel(
    const int* __restrict__ s, const int* __restrict__ sp,
    const float* __restrict__ cw, const float* __restrict__ cb)
{
    __shared__ float tab[14 * 8];
    __shared__ float w[CE_ * SE_ * 9];
    __shared__ float bias[CE_];
    __shared__ float xs[SE_ * 324];   // padded 18x18 per channel
    __shared__ float xd[SE_ * 324];

    int tid = threadIdx.x;
    int b = blockIdx.x;

    if (tid < 112) tab[tid] = g_table[tid];
    for (int i = tid; i < CE_ * SE_ * 9; i += 256) w[i] = cw[i];
    if (tid < CE_) bias[tid] = cb[tid];
    for (int i = tid; i < SE_ * 324; i += 256) { xs[i] = 0.f; xd[i] = 0.f; }
    __syncthreads();

    int py0 = tid >> 4, px0 = tid & 15;
    int sv  = s[(size_t)b * HW + tid];
    int spv = sp[(size_t)b * HW + tid];
    #pragma unroll
    for (int ic = 0; ic < SE_; ic++) {
        float a = tab[sv * 8 + ic];
        float c = tab[spv * 8 + ic];
        int o = ic * 324 + (py0 + 1) * 18 + px0 + 1;
        xs[o] = a;
        xd[o] = c - a;           // conv(x'-x) == sp_e - s_e (bias cancels)
    }
    __syncthreads();

    int ocg = tid >> 6;          // 4 groups of 4 output channels
    int y   = (tid >> 2) & 15;
    int xg  = (tid & 3) * 4;

    float as[4][4] = {}, ad[4][4] = {};
    #pragma unroll
    for (int ic = 0; ic < SE_; ic++) {
        const float* ps = xs + ic * 324 + y * 18 + xg;
        const float* pd = xd + ic * 324 + y * 18 + xg;
        #pragma unroll
        for (int dy = 0; dy < 3; dy++)
        #pragma unroll
        for (int dx = 0; dx < 3; dx++) {
            int off = dy * 18 + dx;
            float s0 = ps[off], s1 = ps[off + 1], s2 = ps[off + 2], s3 = ps[off + 3];
            float d0 = pd[off], d1 = pd[off + 1], d2 = pd[off + 2], d3 = pd[off + 3];
            #pragma unroll
            for (int j = 0; j < 4; j++) {
                float wv = w[(ocg * 4 + j) * 72 + ic * 9 + dy * 3 + dx];
                as[j][0] += wv * s0; as[j][1] += wv * s1; as[j][2] += wv * s2; as[j][3] += wv * s3;
                ad[j][0] += wv * d0; ad[j][1] += wv * d1; ad[j][2] += wv * d2; ad[j][3] += wv * d3;
            }
        }
    }
    #pragma unroll
    for (int j = 0; j < 4; j++) {
        int oc = ocg * 4 + j;
        float bb = bias[oc];
        size_t o = ((size_t)b * CE_ + oc) * HW + y * 16 + xg;
        float4 v1 = make_float4(as[j][0] + bb, as[j][1] + bb, as[j][2] + bb, as[j][3] + bb);
        float4 v2 = make_float4(ad[j][0], ad[j][1], ad[j][2], ad[j][3]);
        *(float4*)(g_se + o) = v1;
        *(float4*)(g_de + o) = v2;
    }
}

// ---------------- fused tower: conv1(16->16)+relu, conv2(16->32)+relu ----------------
#define TOWER_SMEM_FLOATS (5184 * 2 + 2304 + 4608 + 16 + 32)
#define TOWER_SMEM_BYTES  (TOWER_SMEM_FLOATS * 4)

__global__ __launch_bounds__(256) void tower_kernel(
    const float* __restrict__ w1a, const float* __restrict__ b1a,
    const float* __restrict__ w2a, const float* __restrict__ b2a,
    const float* __restrict__ w1b, const float* __restrict__ b1b,
    const float* __restrict__ w2b, const float* __restrict__ b2b)
{
    extern __shared__ float sm[];
    float* pin = sm;                 // 16 * 324
    float* mid = sm + 5184;          // 16 * 324
    float* w1  = sm + 10368;         // 16*16*9
    float* w2  = sm + 12672;         // 32*16*9
    float* bb1 = sm + 17280;         // 16
    float* bb2 = sm + 17296;         // 32

    int tid = threadIdx.x;
    int b   = blockIdx.x;
    int tw  = blockIdx.y;

    const float* in  = tw ? g_de : g_se;
    const float* w1g = tw ? w1b : w1a;
    const float* b1g = tw ? b1b : b1a;
    const float* w2g = tw ? w2b : w2a;
    const float* b2g = tw ? b2b : b2a;

    for (int i = tid; i < 10368; i += 256) sm[i] = 0.f;    // zero pads of pin & mid
    for (int i = tid; i < 2304; i += 256) w1[i] = w1g[i];
    for (int i = tid; i < 4608; i += 256) w2[i] = w2g[i];
    if (tid < 16) bb1[tid] = b1g[tid];
    if (tid < 32) bb2[tid] = b2g[tid];
    __syncthreads();

    int py0 = tid >> 4, px0 = tid & 15;
    #pragma unroll
    for (int c = 0; c < 16; c++)
        pin[c * 324 + (py0 + 1) * 18 + px0 + 1] = in[((size_t)b * 16 + c) * HW + tid];
    __syncthreads();

    int ocg = tid >> 6;
    int y   = (tid >> 2) & 15;
    int xg  = (tid & 3) * 4;

    // conv1: 16 -> 16
    {
        float acc[4][4] = {};
        #pragma unroll
        for (int ic = 0; ic < 16; ic++) {
            const float* pi = pin + ic * 324 + y * 18 + xg;
            #pragma unroll
            for (int dy = 0; dy < 3; dy++)
            #pragma unroll
            for (int dx = 0; dx < 3; dx++) {
                int off = dy * 18 + dx;
                float v0 = pi[off], v1 = pi[off + 1], v2 = pi[off + 2], v3 = pi[off + 3];
                #pragma unroll
                for (int j = 0; j < 4; j++) {
                    float wv = w1[(ocg * 4 + j) * 144 + ic * 9 + dy * 3 + dx];
                    acc[j][0] += wv * v0; acc[j][1] += wv * v1;
                    acc[j][2] += wv * v2; acc[j][3] += wv * v3;
                }
            }
        }
        #pragma unroll
        for (int j = 0; j < 4; j++) {
            int oc = ocg * 4 + j;
            float bbv = bb1[oc];
            float* mp = mid + oc * 324 + (y + 1) * 18 + xg + 1;
            mp[0] = fmaxf(acc[j][0] + bbv, 0.f);
            mp[1] = fmaxf(acc[j][1] + bbv, 0.f);
            mp[2] = fmaxf(acc[j][2] + bbv, 0.f);
            mp[3] = fmaxf(acc[j][3] + bbv, 0.f);
        }
    }
    __syncthreads();

    // conv2: 16 -> 32
    {
        float a2[8][4] = {};
        #pragma unroll 2
        for (int ic = 0; ic < 16; ic++) {
            const float* pi = mid + ic * 324 + y * 18 + xg;
            #pragma unroll
            for (int dy = 0; dy < 3; dy++)
            #pragma unroll
            for (int dx = 0; dx < 3; dx++) {
                int off = dy * 18 + dx;
                float v0 = pi[off], v1 = pi[off + 1], v2 = pi[off + 2], v3 = pi[off + 3];
                #pragma unroll
                for (int j = 0; j < 8; j++) {
                    float wv = w2[(ocg * 8 + j) * 144 + ic * 9 + dy * 3 + dx];
                    a2[j][0] += wv * v0; a2[j][1] += wv * v1;
                    a2[j][2] += wv * v2; a2[j][3] += wv * v3;
                }
            }
        }
        float* act = g_act + (size_t)tw * B_ * 8192;
        #pragma unroll
        for (int j = 0; j < 8; j++) {
            int oc = ocg * 8 + j;
            float bbv = bb2[oc];
            float4 v = make_float4(fmaxf(a2[j][0] + bbv, 0.f), fmaxf(a2[j][1] + bbv, 0.f),
                                   fmaxf(a2[j][2] + bbv, 0.f), fmaxf(a2[j][3] + bbv, 0.f));
            *(float4*)(act + (size_t)b * 8192 + oc * HW + y * 16 + xg) = v;
        }
    }
}

// ---------------- fused dual-tower, split-K=2 linear: part[z] = act_z . w_z^T ----------------
// grid (4, 16, 4): z = tower*2 + khalf. 128x128 tile, K-slice = 4096, lda = 8192.
__global__ __launch_bounds__(256, 2) void linear_kernel(
    const float* __restrict__ act_all,
    const float* __restrict__ w1, const float* __restrict__ w2)
{
    __shared__ float As[2][8][128];
    __shared__ float Bs[2][8][128];

    int tw = blockIdx.z >> 1;
    int kh = blockIdx.z & 1;
    const float* A  = act_all + (size_t)tw * B_ * 8192 + (size_t)kh * 4096;
    const float* Bm = (tw ? w2 : w1) + (size_t)kh * 4096;
    float* C = g_part + (size_t)blockIdx.z * B_ * ESZ_;

    int tid = threadIdx.x;
    int tx = tid & 15, ty = tid >> 4;
    int bm = blockIdx.y * 128, bn = blockIdx.x * 128;

    int lr = tid >> 1;
    int lc = (tid & 1) * 4;
    const float* Ald = A + (size_t)(bm + lr) * 8192 + lc;
    const float* Bld = Bm + (size_t)(bn + lr) * 8192 + lc;

    float4 a4 = *(const float4*)Ald;
    float4 b4 = *(const float4*)Bld;
    As[0][lc + 0][lr] = a4.x; As[0][lc + 1][lr] = a4.y;
    As[0][lc + 2][lr] = a4.z; As[0][lc + 3][lr] = a4.w;
    Bs[0][lc + 0][lr] = b4.x; Bs[0][lc + 1][lr] = b4.y;
    Bs[0][lc + 2][lr] = b4.z; Bs[0][lc + 3][lr] = b4.w;
    __syncthreads();

    float acc[8][8] = {};
    const int nk = 4096 / 8;
    for (int kt = 0; kt < nk; kt++) {
        int buf = kt & 1;
        if (kt + 1 < nk) {
            a4 = *(const float4*)(Ald + (size_t)(kt + 1) * 8);
            b4 = *(const float4*)(Bld + (size_t)(kt + 1) * 8);
        }
        #pragma unroll
        for (int kk = 0; kk < 8; kk++) {
            float ar[8], brr[8];
            *(float4*)&ar[0]  = *(const float4*)&As[buf][kk][ty * 8];
            *(float4*)&ar[4]  = *(const float4*)&As[buf][kk][ty * 8 + 4];
            *(float4*)&brr[0] = *(const float4*)&Bs[buf][kk][tx * 8];
            *(float4*)&brr[4] = *(const float4*)&Bs[buf][kk][tx * 8 + 4];
            #pragma unroll
            for (int i = 0; i < 8; i++)
                #pragma unroll
                for (int j = 0; j < 8; j++)
                    acc[i][j] += ar[i] * brr[j];
        }
        if (kt + 1 < nk) {
            int nb = buf ^ 1;
            As[nb][lc + 0][lr] = a4.x; As[nb][lc + 1][lr] = a4.y;
            As[nb][lc + 2][lr] = a4.z; As[nb][lc + 3][lr] = a4.w;
            Bs[nb][lc + 0][lr] = b4.x; Bs[nb][lc + 1][lr] = b4.y;
            Bs[nb][lc + 2][lr] = b4.z; Bs[nb][lc + 3][lr] = b4.w;
        }
        __syncthreads();
    }

    #pragma unroll
    for (int i = 0; i < 8; i++) {
        float* cp = C + (size_t)(bm + ty * 8 + i) * ESZ_ + bn + tx * 8;
        *(float4*)cp       = *(float4*)&acc[i][0];
        *(float4*)(cp + 4) = *(float4*)&acc[i][4];
    }
}

// ---------------- split-K reduce + bias + L2 normalize (eps=1e-4), writes g_embed ----------------
__global__ __launch_bounds__(128) void reduce_norm_kernel(
    const float* __restrict__ b1, const float* __restrict__ b2)
{
    int row = blockIdx.x;            // 0..4095
    int tw  = row >> 11;
    int r   = row & 2047;
    const float* p0 = g_part + ((size_t)(tw * 2) * B_ + r) * ESZ_;
    const float* p1 = p0 + (size_t)B_ * ESZ_;
    const float* bias = tw ? b2 : b1;
    int t = threadIdx.x;

    __shared__ float red[128];
    float4 a = *(const float4*)(p0 + t * 4);
    float4 b = *(const float4*)(p1 + t * 4);
    float4 bb = *(const float4*)(bias + t * 4);
    float v0 = a.x + b.x + bb.x;
    float v1 = a.y + b.y + bb.y;
    float v2 = a.z + b.z + bb.z;
    float v3 = a.w + b.w + bb.w;
    red[t] = v0 * v0 + v1 * v1 + v2 * v2 + v3 * v3;
    __syncthreads();
    for (int off = 64; off > 0; off >>= 1) {
        if (t < off) red[t] += red[t + off];
        __syncthreads();
    }
    float inv = 1.0f / (sqrtf(red[0]) + 1e-4f);
    float* e = g_embed + (size_t)row * ESZ_;
    *(float4*)(e + t * 4) = make_float4(v0 * inv, v1 * inv, v2 * inv, v3 * inv);
}

// ---------------- generic SGEMM: C[M,N] = alpha * A[M,K] . B[N,K]^T, optional B-row gather ----------------
template<bool GATHER, bool SCALE>
__global__ __launch_bounds__(256, 2) void sgemm_kernel(
    const float* __restrict__ A, const float* __restrict__ Bm,
    float* __restrict__ C, int M, int N, int K)
{
    __shared__ float As[2][8][128];
    __shared__ float Bs[2][8][128];

    int tid = threadIdx.x;
    int tx = tid & 15, ty = tid >> 4;
    int bm = blockIdx.y * 128, bn = blockIdx.x * 128;

    int lr = tid >> 1;
    int lc = (tid & 1) * 4;
    const float* Ald = A + (size_t)(bm + lr) * K + lc;
    int brw = GATHER ? g_zind[bn + lr] : (bn + lr);
    const float* Bld = Bm + (size_t)brw * K + lc;

    float4 a4 = *(const float4*)Ald;
    float4 b4 = *(const float4*)Bld;
    As[0][lc + 0][lr] = a4.x; As[0][lc + 1][lr] = a4.y;
    As[0][lc + 2][lr] = a4.z; As[0][lc + 3][lr] = a4.w;
    Bs[0][lc + 0][lr] = b4.x; Bs[0][lc + 1][lr] = b4.y;
    Bs[0][lc + 2][lr] = b4.z; Bs[0][lc + 3][lr] = b4.w;
    __syncthreads();

    float acc[8][8] = {};
    int nk = K >> 3;
    for (int kt = 0; kt < nk; kt++) {
        int buf = kt & 1;
        if (kt + 1 < nk) {
            a4 = *(const float4*)(Ald + (size_t)(kt + 1) * 8);
            b4 = *(const float4*)(Bld + (size_t)(kt + 1) * 8);
        }
        #pragma unroll
        for (int kk = 0; kk < 8; kk++) {
            float ar[8], brr[8];
            *(float4*)&ar[0]  = *(const float4*)&As[buf][kk][ty * 8];
            *(float4*)&ar[4]  = *(const float4*)&As[buf][kk][ty * 8 + 4];
            *(float4*)&brr[0] = *(const float4*)&Bs[buf][kk][tx * 8];
            *(float4*)&brr[4] = *(const float4*)&Bs[buf][kk][tx * 8 + 4];
            #pragma unroll
            for (int i = 0; i < 8; i++)
                #pragma unroll
                for (int j = 0; j < 8; j++)
                    acc[i][j] += ar[i] * brr[j];
        }
        if (kt + 1 < nk) {
            int nb = buf ^ 1;
            As[nb][lc + 0][lr] = a4.x; As[nb][lc + 1][lr] = a4.y;
            As[nb][lc + 2][lr] = a4.z; As[nb][lc + 3][lr] = a4.w;
            Bs[nb][lc + 0][lr] = b4.x; Bs[nb][lc + 1][lr] = b4.y;
            Bs[nb][lc + 2][lr] = b4.z; Bs[nb][lc + 3][lr] = b4.w;
        }
        __syncthreads();
    }

    float alpha = SCALE ? g_escale : 1.0f;
    #pragma unroll
    for (int i = 0; i < 8; i++) {
        float* cp = C + (size_t)(bm + ty * 8 + i) * N + bn + tx * 8;
        float4 o0, o1;
        o0.x = acc[i][0] * alpha; o0.y = acc[i][1] * alpha;
        o0.z = acc[i][2] * alpha; o0.w = acc[i][3] * alpha;
        o1.x = acc[i][4] * alpha; o1.y = acc[i][5] * alpha;
        o1.z = acc[i][6] * alpha; o1.w = acc[i][7] * alpha;
        *(float4*)cp = o0;
        *(float4*)(cp + 4) = o1;
    }
}

// ---------------- argmax over scores rows (first-max tie-break, matches jnp.argmax) ----------------
__global__ void argmax_kernel()
{
    int r = blockIdx.x, t = threadIdx.x;
    const float* sr = g_scores + (size_t)r * NZ_;
    __shared__ float sv[256];
    __shared__ int   si[256];
    float v0 = sr[t], v1 = sr[t + 256];
    float bv = v0; int bi = t;
    if (v1 > bv) { bv = v1; bi = t + 256; }
    sv[t] = bv; si[t] = bi; __syncthreads();
    for (int off = 128; off > 0; off >>= 1) {
        if (t < off) {
            float ov = sv[t + off]; int oi = si[t + off];
            if (ov > sv[t] || (ov == sv[t] && oi < si[t])) { sv[t] = ov; si[t] = oi; }
        }
        __syncthreads();
    }
    if (t == 0) g_zind[r] = si[0];
}

// ---------------- launch ----------------
extern "C" void kernel_launch(void* const* d_in, const int* in_sizes, int n_in,
                              void* d_out, int out_size)
{
    (void)in_sizes; (void)n_in; (void)out_size;
    const int*   s       = (const int*)d_in[0];
    const int*   sp      = (const int*)d_in[1];
    const float* state_e = (const float*)d_in[2];
    const float* cew     = (const float*)d_in[3];
    const float* ceb     = (const float*)d_in[4];
    const float* p1c1w   = (const float*)d_in[5];
    const float* p1c1b   = (const float*)d_in[6];
    const float* p1c2w   = (const float*)d_in[7];
    const float* p1c2b   = (const float*)d_in[8];
    const float* p1lw    = (const float*)d_in[9];
    const float* p1lb    = (const float*)d_in[10];
    const float* p2c1w   = (const float*)d_in[11];
    const float* p2c1b   = (const float*)d_in[12];
    const float* p2c2w   = (const float*)d_in[13];
    const float* p2c2b   = (const float*)d_in[14];
    const float* p2lw    = (const float*)d_in[15];
    const float* p2lb    = (const float*)d_in[16];
    const float* zv      = (const float*)d_in[17];
    const float* scale   = (const float*)d_in[18];

    void *pa, *pe, *pz, *ps;
    cudaGetSymbolAddress(&pa, g_act);
    cudaGetSymbolAddress(&pe, g_embed);
    cudaGetSymbolAddress(&pz, g_zn);
    cudaGetSymbolAddress(&ps, g_scores);
    float* act    = (float*)pa;
    float* emb    = (float*)pe;
    float* zn     = (float*)pz;
    float* scores = (float*)ps;

    cudaFuncSetAttribute(tower_kernel,
                         cudaFuncAttributeMaxDynamicSharedMemorySize, TOWER_SMEM_BYTES);

    prep_kernel<<<513, 128>>>(state_e, zv, scale);
    embed_kernel<<<B_, 256>>>(s, sp, cew, ceb);
    tower_kernel<<<dim3(B_, 2), 256, TOWER_SMEM_BYTES>>>(
        p1c1w, p1c1b, p1c2w, p1c2b, p2c1w, p2c1b, p2c2w, p2c2b);

    // both tower linears (8192 -> 512) in one launch, split-K = 2 -> 256 blocks
    linear_kernel<<<dim3(4, 16, 4), 256>>>(act, p1lw, p2lw);

    // split-K reduce + bias + normalize -> g_embed (both towers)
    reduce_norm_kernel<<<2 * B_, 128>>>(p1lb, p2lb);

    // scores = embed2 . zn^T
    sgemm_kernel<false, false><<<dim3(4, 16), 256>>>(
        emb + (size_t)B_ * ESZ_, zn, scores, B_, NZ_, ESZ_);

    argmax_kernel<<<B_, 256>>>();

    // out = exp(scale) * embed1 . zn[z_inds]^T
    sgemm_kernel<true, true><<<dim3(16, 16), 256>>>(
        emb, zn, (float*)d_out, B_, B_, ESZ_);
}

// round 4
// speedup vs baseline: 2.1195x; 1.1580x over previous
#include <cuda_runtime.h>
#include <cuda_bf16.h>
#include <cstdint>
#include <math.h>

// Problem constants
#define B_    2048
#define HW    256
#define SE_   8
#define CE_   16
#define ESZ_  512
#define NZ_   512

// ---------------- scratch (static device globals; no allocation) ----------------
__device__ float g_table[14 * 8];
__device__ float g_zn[NZ_ * ESZ_];
__device__ float g_se[(size_t)B_ * CE_ * HW];
__device__ float g_de[(size_t)B_ * CE_ * HW];
__device__ __nv_bfloat16 g_ahi[2 * (size_t)B_ * 8192];
__device__ __nv_bfloat16 g_alo[2 * (size_t)B_ * 8192];
__device__ __nv_bfloat16 g_whi[2 * (size_t)ESZ_ * 8192];
__device__ __nv_bfloat16 g_wlo[2 * (size_t)ESZ_ * 8192];
__device__ float g_part[2 * (size_t)B_ * ESZ_];
__device__ float g_embed[2 * (size_t)B_ * ESZ_];
__device__ float g_scores[(size_t)B_ * NZ_];
__device__ int   g_zind[B_];
__device__ float g_escale;

__device__ __forceinline__ uint32_t smem_u32(const void* p) {
    uint32_t a;
    asm("{ .reg .u64 t; cvta.to.shared.u64 t, %1; cvt.u32.u64 %0, t; }" : "=r"(a) : "l"(p));
    return a;
}

#define LDMATRIX_X4(r0, r1, r2, r3, addr) \
    asm volatile("ldmatrix.sync.aligned.m8n8.x4.shared.b16 {%0,%1,%2,%3}, [%4];" \
        : "=r"(r0), "=r"(r1), "=r"(r2), "=r"(r3) : "r"(addr))

#define MMA_BF16(d, a, b0, b1) \
    asm volatile("mma.sync.aligned.m16n8k16.row.col.f32.bf16.bf16.f32 " \
        "{%0,%1,%2,%3}, {%4,%5,%6,%7}, {%8,%9}, {%0,%1,%2,%3};" \
        : "+f"((d)[0]), "+f"((d)[1]), "+f"((d)[2]), "+f"((d)[3]) \
        : "r"((a)[0]), "r"((a)[1]), "r"((a)[2]), "r"((a)[3]), "r"(b0), "r"(b1))

#define CP_ASYNC16(dst, src) \
    asm volatile("cp.async.cg.shared.global [%0], [%1], 16;" :: "r"(dst), "l"(src) : "memory")

// ---------------- prep: normalize z rows, embedding table, exp(scale) ----------------
__global__ void prep_kernel(const float* __restrict__ state_embed,
                            const float* __restrict__ zv,
                            const float* __restrict__ scale)
{
    int t = threadIdx.x;
    int blk = blockIdx.x;
    if (blk < NZ_) {
        __shared__ float red[128];
        const float* zr = zv + (size_t)blk * ESZ_;
        float v[4];
        float s = 0.f;
        #pragma unroll
        for (int i = 0; i < 4; i++) { v[i] = zr[t + i * 128]; s += v[i] * v[i]; }
        red[t] = s; __syncthreads();
        for (int off = 64; off > 0; off >>= 1) {
            if (t < off) red[t] += red[t + off];
            __syncthreads();
        }
        float inv = 1.0f / sqrtf(red[0]);
        float* o = g_zn + (size_t)blk * ESZ_;
        #pragma unroll
        for (int i = 0; i < 4; i++) o[t + i * 128] = v[i] * inv;
    } else {
        if (t < 14) {
            float s = 0.f;
            #pragma unroll
            for (int j = 0; j < 8; j++) { float x = state_embed[t * 8 + j]; s += x * x; }
            float d = fmaxf(sqrtf(s), 1.0f);
            #pragma unroll
            for (int j = 0; j < 8; j++) g_table[t * 8 + j] = state_embed[t * 8 + j] / d;
        }
        if (t == 0) g_escale = expf(scale[0]);
    }
}

// ---------------- embed gather + 3x3 conv (8ch -> 16ch), fused for s and (s'-s) ----------------
__global__ __launch_bounds__(256) void embed_kernel(
    const int* __restrict__ s, const int* __restrict__ sp,
    const float* __restrict__ cw, const float* __restrict__ cb)
{
    __shared__ float tab[14 * 8];
    __shared__ float w[CE_ * SE_ * 9];
    __shared__ float bias[CE_];
    __shared__ float xs[SE_ * 324];
    __shared__ float xd[SE_ * 324];

    int tid = threadIdx.x;
    int b = blockIdx.x;

    if (tid < 112) tab[tid] = g_table[tid];
    for (int i = tid; i < CE_ * SE_ * 9; i += 256) w[i] = cw[i];
    if (tid < CE_) bias[tid] = cb[tid];
    for (int i = tid; i < SE_ * 324; i += 256) { xs[i] = 0.f; xd[i] = 0.f; }
    __syncthreads();

    int py0 = tid >> 4, px0 = tid & 15;
    int sv  = s[(size_t)b * HW + tid];
    int spv = sp[(size_t)b * HW + tid];
    #pragma unroll
    for (int ic = 0; ic < SE_; ic++) {
        float a = tab[sv * 8 + ic];
        float c = tab[spv * 8 + ic];
        int o = ic * 324 + (py0 + 1) * 18 + px0 + 1;
        xs[o] = a;
        xd[o] = c - a;
    }
    __syncthreads();

    int ocg = tid >> 6;
    int y   = (tid >> 2) & 15;
    int xg  = (tid & 3) * 4;

    float as[4][4] = {}, ad[4][4] = {};
    #pragma unroll
    for (int ic = 0; ic < SE_; ic++) {
        const float* ps = xs + ic * 324 + y * 18 + xg;
        const float* pd = xd + ic * 324 + y * 18 + xg;
        #pragma unroll
        for (int dy = 0; dy < 3; dy++)
        #pragma unroll
        for (int dx = 0; dx < 3; dx++) {
            int off = dy * 18 + dx;
            float s0 = ps[off], s1 = ps[off + 1], s2 = ps[off + 2], s3 = ps[off + 3];
            float d0 = pd[off], d1 = pd[off + 1], d2 = pd[off + 2], d3 = pd[off + 3];
            #pragma unroll
            for (int j = 0; j < 4; j++) {
                float wv = w[(ocg * 4 + j) * 72 + ic * 9 + dy * 3 + dx];
                as[j][0] += wv * s0; as[j][1] += wv * s1; as[j][2] += wv * s2; as[j][3] += wv * s3;
                ad[j][0] += wv * d0; ad[j][1] += wv * d1; ad[j][2] += wv * d2; ad[j][3] += wv * d3;
            }
        }
    }
    #pragma unroll
    for (int j = 0; j < 4; j++) {
        int oc = ocg * 4 + j;
        float bb = bias[oc];
        size_t o = ((size_t)b * CE_ + oc) * HW + y * 16 + xg;
        float4 v1 = make_float4(as[j][0] + bb, as[j][1] + bb, as[j][2] + bb, as[j][3] + bb);
        float4 v2 = make_float4(ad[j][0], ad[j][1], ad[j][2], ad[j][3]);
        *(float4*)(g_se + o) = v1;
        *(float4*)(g_de + o) = v2;
    }
}

// ---------------- fused tower: conv1+relu, conv2+relu, emits bf16 hi/lo ----------------
#define TOWER_SMEM_FLOATS (5184 * 2 + 2304 + 4608 + 16 + 32)
#define TOWER_SMEM_BYTES  (TOWER_SMEM_FLOATS * 4)

__global__ __launch_bounds__(256) void tower_kernel(
    const float* __restrict__ w1a, const float* __restrict__ b1a,
    const float* __restrict__ w2a, const float* __restrict__ b2a,
    const float* __restrict__ w1b, const float* __restrict__ b1b,
    const float* __restrict__ w2b, const float* __restrict__ b2b)
{
    extern __shared__ float sm[];
    float* pin = sm;
    float* mid = sm + 5184;
    float* w1  = sm + 10368;
    float* w2  = sm + 12672;
    float* bb1 = sm + 17280;
    float* bb2 = sm + 17296;

    int tid = threadIdx.x;
    int b   = blockIdx.x;
    int tw  = blockIdx.y;

    const float* in  = tw ? g_de : g_se;
    const float* w1g = tw ? w1b : w1a;
    const float* b1g = tw ? b1b : b1a;
    const float* w2g = tw ? w2b : w2a;
    const float* b2g = tw ? b2b : b2a;

    for (int i = tid; i < 10368; i += 256) sm[i] = 0.f;
    for (int i = tid; i < 2304; i += 256) w1[i] = w1g[i];
    for (int i = tid; i < 4608; i += 256) w2[i] = w2g[i];
    if (tid < 16) bb1[tid] = b1g[tid];
    if (tid < 32) bb2[tid] = b2g[tid];
    __syncthreads();

    int py0 = tid >> 4, px0 = tid & 15;
    #pragma unroll
    for (int c = 0; c < 16; c++)
        pin[c * 324 + (py0 + 1) * 18 + px0 + 1] = in[((size_t)b * 16 + c) * HW + tid];
    __syncthreads();

    int ocg = tid >> 6;
    int y   = (tid >> 2) & 15;
    int xg  = (tid & 3) * 4;

    {
        float acc[4][4] = {};
        #pragma unroll
        for (int ic = 0; ic < 16; ic++) {
            const float* pi = pin + ic * 324 + y * 18 + xg;
            #pragma unroll
            for (int dy = 0; dy < 3; dy++)
            #pragma unroll
            for (int dx = 0; dx < 3; dx++) {
                int off = dy * 18 + dx;
                float v0 = pi[off], v1 = pi[off + 1], v2 = pi[off + 2], v3 = pi[off + 3];
                #pragma unroll
                for (int j = 0; j < 4; j++) {
                    float wv = w1[(ocg * 4 + j) * 144 + ic * 9 + dy * 3 + dx];
                    acc[j][0] += wv * v0; acc[j][1] += wv * v1;
                    acc[j][2] += wv * v2; acc[j][3] += wv * v3;
                }
            }
        }
        #pragma unroll
        for (int j = 0; j < 4; j++) {
            int oc = ocg * 4 + j;
            float bbv = bb1[oc];
            float* mp = mid + oc * 324 + (y + 1) * 18 + xg + 1;
            mp[0] = fmaxf(acc[j][0] + bbv, 0.f);
            mp[1] = fmaxf(acc[j][1] + bbv, 0.f);
            mp[2] = fmaxf(acc[j][2] + bbv, 0.f);
            mp[3] = fmaxf(acc[j][3] + bbv, 0.f);
        }
    }
    __syncthreads();

    {
        float a2[8][4] = {};
        #pragma unroll 2
        for (int ic = 0; ic < 16; ic++) {
            const float* pi = mid + ic * 324 + y * 18 + xg;
            #pragma unroll
            for (int dy = 0; dy < 3; dy++)
            #pragma unroll
            for (int dx = 0; dx < 3; dx++) {
                int off = dy * 18 + dx;
                float v0 = pi[off], v1 = pi[off + 1], v2 = pi[off + 2], v3 = pi[off + 3];
                #pragma unroll
                for (int j = 0; j < 8; j++) {
                    float wv = w2[(ocg * 8 + j) * 144 + ic * 9 + dy * 3 + dx];
                    a2[j][0] += wv * v0; a2[j][1] += wv * v1;
                    a2[j][2] += wv * v2; a2[j][3] += wv * v3;
                }
            }
        }
        size_t base = (size_t)tw * B_ * 8192 + (size_t)b * 8192;
        #pragma unroll
        for (int j = 0; j < 8; j++) {
            int oc = ocg * 8 + j;
            float bbv = bb2[oc];
            float v[4];
            v[0] = fmaxf(a2[j][0] + bbv, 0.f);
            v[1] = fmaxf(a2[j][1] + bbv, 0.f);
            v[2] = fmaxf(a2[j][2] + bbv, 0.f);
            v[3] = fmaxf(a2[j][3] + bbv, 0.f);
            __nv_bfloat16 h[4], l[4];
            #pragma unroll
            for (int q = 0; q < 4; q++) {
                h[q] = __float2bfloat16(v[q]);
                l[q] = __float2bfloat16(v[q] - __bfloat162float(h[q]));
            }
            size_t o = base + oc * HW + y * 16 + xg;
            *(__nv_bfloat162*)(g_ahi + o)     = __nv_bfloat162(h[0], h[1]);
            *(__nv_bfloat162*)(g_ahi + o + 2) = __nv_bfloat162(h[2], h[3]);
            *(__nv_bfloat162*)(g_alo + o)     = __nv_bfloat162(l[0], l[1]);
            *(__nv_bfloat162*)(g_alo + o + 2) = __nv_bfloat162(l[2], l[3]);
        }
    }
}

// ---------------- weight split fp32 -> bf16 hi/lo ----------------
__global__ __launch_bounds__(256) void wconv_kernel(
    const float* __restrict__ w1, const float* __restrict__ w2)
{
    size_t i4 = (size_t)blockIdx.x * 256 + threadIdx.x;     // float4 index
    const size_t half4 = (size_t)ESZ_ * 8192 / 4;
    const float* src = (i4 < half4) ? w1 : w2;
    size_t loc4 = (i4 < half4) ? i4 : i4 - half4;
    float4 v = *(const float4*)(src + loc4 * 4);
    float vv[4] = { v.x, v.y, v.z, v.w };
    __nv_bfloat16 h[4], l[4];
    #pragma unroll
    for (int q = 0; q < 4; q++) {
        h[q] = __float2bfloat16(vv[q]);
        l[q] = __float2bfloat16(vv[q] - __bfloat162float(h[q]));
    }
    size_t o = i4 * 4;
    *(__nv_bfloat162*)(g_whi + o)     = __nv_bfloat162(h[0], h[1]);
    *(__nv_bfloat162*)(g_whi + o + 2) = __nv_bfloat162(h[2], h[3]);
    *(__nv_bfloat162*)(g_wlo + o)     = __nv_bfloat162(l[0], l[1]);
    *(__nv_bfloat162*)(g_wlo + o + 2) = __nv_bfloat162(l[2], l[3]);
}

// ---------------- HMMA bf16-split linear: part[tw] = act . W^T (hi/lo, 3-term) ----------------
// grid (4, 16, 2). Block 128x128, K-tile 32, virtual K = 3*8192 -> 768 iters.
// 8 warps: warp w -> (mw = w&1)*64 rows, (nw = w>>1)*32 cols.
#define LIN_NK 768
#define APITCH 40   // bf16 elements per smem row (80B, conflict-free ldmatrix)

__global__ __launch_bounds__(256, 2) void hmma_linear_kernel()
{
    __shared__ __align__(16) __nv_bfloat16 smA[2][128 * APITCH];
    __shared__ __align__(16) __nv_bfloat16 smW[2][128 * APITCH];

    int tid = threadIdx.x;
    int wid = tid >> 5;
    int lid = tid & 31;
    int bn = blockIdx.x * 128;
    int bm = blockIdx.y * 128;
    int tw = blockIdx.z;

    const __nv_bfloat16* Ahi = g_ahi + (size_t)tw * B_ * 8192;
    const __nv_bfloat16* Alo = g_alo + (size_t)tw * B_ * 8192;
    const __nv_bfloat16* Whi = g_whi + (size_t)tw * ESZ_ * 8192;
    const __nv_bfloat16* Wlo = g_wlo + (size_t)tw * ESZ_ * 8192;

    // loader role
    bool isA = tid < 128;
    int lrow = tid & 127;
    const __nv_bfloat16* srcHi = isA ? (Ahi + (size_t)(bm + lrow) * 8192)
                                     : (Whi + (size_t)(bn + lrow) * 8192);
    const __nv_bfloat16* srcLo = isA ? (Alo + (size_t)(bm + lrow) * 8192)
                                     : (Wlo + (size_t)(bn + lrow) * 8192);
    uint32_t dstBase[2];
    dstBase[0] = smem_u32(isA ? &smA[0][0] : &smW[0][0]) + lrow * (APITCH * 2);
    dstBase[1] = smem_u32(isA ? &smA[1][0] : &smW[1][0]) + lrow * (APITCH * 2);

    auto load_tile = [&](int buf, int kt) {
        int ph = kt >> 8;                 // 0: hi*hi, 1: lo*hi, 2: hi*lo
        int ko = (kt & 255) * 32;
        const __nv_bfloat16* src =
            (isA ? (ph == 1 ? srcLo : srcHi) : (ph == 2 ? srcLo : srcHi)) + ko;
        uint32_t d = dstBase[buf];
        CP_ASYNC16(d,      src);
        CP_ASYNC16(d + 16, src + 8);
        CP_ASYNC16(d + 32, src + 16);
        CP_ASYNC16(d + 48, src + 24);
        asm volatile("cp.async.commit_group;" ::: "memory");
    };

    // fragment smem offsets (bytes) for this lane
    int mw = wid & 1, nw = wid >> 1;
    uint32_t aOff[4], bOff[2];
    #pragma unroll
    for (int mt = 0; mt < 4; mt++) {
        int row = mw * 64 + mt * 16 + (lid & 15);
        int k   = (lid >> 4) * 8;
        aOff[mt] = (uint32_t)(row * APITCH + k) * 2;
    }
    #pragma unroll
    for (int p = 0; p < 2; p++) {
        int n = nw * 32 + p * 16 + ((lid >> 4) & 1) * 8 + (lid & 7);
        int k = ((lid >> 3) & 1) * 8;
        bOff[p] = (uint32_t)(n * APITCH + k) * 2;
    }
    uint32_t aBase[2] = { smem_u32(&smA[0][0]), smem_u32(&smA[1][0]) };
    uint32_t bBase[2] = { smem_u32(&smW[0][0]), smem_u32(&smW[1][0]) };

    float acc[4][4][4] = {};

    load_tile(0, 0);
    for (int kt = 0; kt < LIN_NK; kt++) {
        int buf = kt & 1;
        if (kt + 1 < LIN_NK) {
            load_tile(buf ^ 1, kt + 1);
            asm volatile("cp.async.wait_group 1;" ::: "memory");
        } else {
            asm volatile("cp.async.wait_group 0;" ::: "memory");
        }
        __syncthreads();

        #pragma unroll
        for (int kh = 0; kh < 2; kh++) {
            uint32_t aF[4][4], bF[2][4];
            #pragma unroll
            for (int mt = 0; mt < 4; mt++)
                LDMATRIX_X4(aF[mt][0], aF[mt][1], aF[mt][2], aF[mt][3],
                            aBase[buf] + aOff[mt] + kh * 32);
            #pragma unroll
            for (int p = 0; p < 2; p++)
                LDMATRIX_X4(bF[p][0], bF[p][1], bF[p][2], bF[p][3],
                            bBase[buf] + bOff[p] + kh * 32);
            #pragma unroll
            for (int mt = 0; mt < 4; mt++)
                #pragma unroll
                for (int nt = 0; nt < 4; nt++)
                    MMA_BF16(acc[mt][nt], aF[mt],
                             bF[nt >> 1][(nt & 1) * 2], bF[nt >> 1][(nt & 1) * 2 + 1]);
        }
        __syncthreads();
    }

    // epilogue -> g_part
    float* part = g_part + (size_t)tw * B_ * ESZ_;
    int g = lid >> 2, tg = lid & 3;
    #pragma unroll
    for (int mt = 0; mt < 4; mt++) {
        int row = bm + mw * 64 + mt * 16 + g;
        #pragma unroll
        for (int nt = 0; nt < 4; nt++) {
            int col = bn + nw * 32 + nt * 8 + tg * 2;
            float2 v0 = make_float2(acc[mt][nt][0], acc[mt][nt][1]);
            float2 v1 = make_float2(acc[mt][nt][2], acc[mt][nt][3]);
            *(float2*)(part + (size_t)row * ESZ_ + col)       = v0;
            *(float2*)(part + (size_t)(row + 8) * ESZ_ + col) = v1;
        }
    }
}

// ---------------- bias + L2 normalize (eps=1e-4), writes g_embed ----------------
__global__ __launch_bounds__(128) void reduce_norm_kernel(
    const float* __restrict__ b1, const float* __restrict__ b2)
{
    int row = blockIdx.x;            // 0..4095
    int tw  = row >> 11;
    const float* p = g_part + (size_t)tw * B_ * ESZ_ + (size_t)(row & 2047) * ESZ_;
    const float* bias = tw ? b2 : b1;
    int t = threadIdx.x;

    __shared__ float red[128];
    float4 a  = *(const float4*)(p + t * 4);
    float4 bb = *(const float4*)(bias + t * 4);
    float v0 = a.x + bb.x, v1 = a.y + bb.y, v2 = a.z + bb.z, v3 = a.w + bb.w;
    red[t] = v0 * v0 + v1 * v1 + v2 * v2 + v3 * v3;
    __syncthreads();
    for (int off = 64; off > 0; off >>= 1) {
        if (t < off) red[t] += red[t + off];
        __syncthreads();
    }
    float inv = 1.0f / (sqrtf(red[0]) + 1e-4f);
    float* e = g_embed + (size_t)row * ESZ_;
    *(float4*)(e + t * 4) = make_float4(v0 * inv, v1 * inv, v2 * inv, v3 * inv);
}

// ---------------- generic SGEMM: C[M,N] = alpha * A[M,K] . B[N,K]^T, optional B-row gather ----------------
template<bool GATHER, bool SCALE>
__global__ __launch_bounds__(256, 2) void sgemm_kernel(
    const float* __restrict__ A, const float* __restrict__ Bm,
    float* __restrict__ C, int M, int N, int K)
{
    __shared__ float As[2][8][128];
    __shared__ float Bs[2][8][128];

    int tid = threadIdx.x;
    int tx = tid & 15, ty = tid >> 4;
    int bm = blockIdx.y * 128, bn = blockIdx.x * 128;

    int lr = tid >> 1;
    int lc = (tid & 1) * 4;
    const float* Ald = A + (size_t)(bm + lr) * K + lc;
    int brw = GATHER ? g_zind[bn + lr] : (bn + lr);
    const float* Bld = Bm + (size_t)brw * K + lc;

    float4 a4 = *(const float4*)Ald;
    float4 b4 = *(const float4*)Bld;
    As[0][lc + 0][lr] = a4.x; As[0][lc + 1][lr] = a4.y;
    As[0][lc + 2][lr] = a4.z; As[0][lc + 3][lr] = a4.w;
    Bs[0][lc + 0][lr] = b4.x; Bs[0][lc + 1][lr] = b4.y;
    Bs[0][lc + 2][lr] = b4.z; Bs[0][lc + 3][lr] = b4.w;
    __syncthreads();

    float acc[8][8] = {};
    int nk = K >> 3;
    for (int kt = 0; kt < nk; kt++) {
        int buf = kt & 1;
        if (kt + 1 < nk) {
            a4 = *(const float4*)(Ald + (size_t)(kt + 1) * 8);
            b4 = *(const float4*)(Bld + (size_t)(kt + 1) * 8);
        }
        #pragma unroll
        for (int kk = 0; kk < 8; kk++) {
            float ar[8], brr[8];
            *(float4*)&ar[0]  = *(const float4*)&As[buf][kk][ty * 8];
            *(float4*)&ar[4]  = *(const float4*)&As[buf][kk][ty * 8 + 4];
            *(float4*)&brr[0] = *(const float4*)&Bs[buf][kk][tx * 8];
            *(float4*)&brr[4] = *(const float4*)&Bs[buf][kk][tx * 8 + 4];
            #pragma unroll
            for (int i = 0; i < 8; i++)
                #pragma unroll
                for (int j = 0; j < 8; j++)
                    acc[i][j] += ar[i] * brr[j];
        }
        if (kt + 1 < nk) {
            int nb = buf ^ 1;
            As[nb][lc + 0][lr] = a4.x; As[nb][lc + 1][lr] = a4.y;
            As[nb][lc + 2][lr] = a4.z; As[nb][lc + 3][lr] = a4.w;
            Bs[nb][lc + 0][lr] = b4.x; Bs[nb][lc + 1][lr] = b4.y;
            Bs[nb][lc + 2][lr] = b4.z; Bs[nb][lc + 3][lr] = b4.w;
        }
        __syncthreads();
    }

    float alpha = SCALE ? g_escale : 1.0f;
    #pragma unroll
    for (int i = 0; i < 8; i++) {
        float* cp = C + (size_t)(bm + ty * 8 + i) * N + bn + tx * 8;
        float4 o0, o1;
        o0.x = acc[i][0] * alpha; o0.y = acc[i][1] * alpha;
        o0.z = acc[i][2] * alpha; o0.w = acc[i][3] * alpha;
        o1.x = acc[i][4] * alpha; o1.y = acc[i][5] * alpha;
        o1.z = acc[i][6] * alpha; o1.w = acc[i][7] * alpha;
        *(float4*)cp = o0;
        *(float4*)(cp + 4) = o1;
    }
}

// ---------------- argmax over scores rows (first-max tie-break) ----------------
__global__ void argmax_kernel()
{
    int r = blockIdx.x, t = threadIdx.x;
    const float* sr = g_scores + (size_t)r * NZ_;
    __shared__ float sv[256];
    __shared__ int   si[256];
    float v0 = sr[t], v1 = sr[t + 256];
    float bv = v0; int bi = t;
    if (v1 > bv) { bv = v1; bi = t + 256; }
    sv[t] = bv; si[t] = bi; __syncthreads();
    for (int off = 128; off > 0; off >>= 1) {
        if (t < off) {
            float ov = sv[t + off]; int oi = si[t + off];
            if (ov > sv[t] || (ov == sv[t] && oi < si[t])) { sv[t] = ov; si[t] = oi; }
        }
        __syncthreads();
    }
    if (t == 0) g_zind[r] = si[0];
}

// ---------------- launch ----------------
extern "C" void kernel_launch(void* const* d_in, const int* in_sizes, int n_in,
                              void* d_out, int out_size)
{
    (void)in_sizes; (void)n_in; (void)out_size;
    const int*   s       = (const int*)d_in[0];
    const int*   sp      = (const int*)d_in[1];
    const float* state_e = (const float*)d_in[2];
    const float* cew     = (const float*)d_in[3];
    const float* ceb     = (const float*)d_in[4];
    const float* p1c1w   = (const float*)d_in[5];
    const float* p1c1b   = (const float*)d_in[6];
    const float* p1c2w   = (const float*)d_in[7];
    const float* p1c2b   = (const float*)d_in[8];
    const float* p1lw    = (const float*)d_in[9];
    const float* p1lb    = (const float*)d_in[10];
    const float* p2c1w   = (const float*)d_in[11];
    const float* p2c1b   = (const float*)d_in[12];
    const float* p2c2w   = (const float*)d_in[13];
    const float* p2c2b   = (const float*)d_in[14];
    const float* p2lw    = (const float*)d_in[15];
    const float* p2lb    = (const float*)d_in[16];
    const float* zv      = (const float*)d_in[17];
    const float* scale   = (const float*)d_in[18];

    void *pe, *pz, *ps;
    cudaGetSymbolAddress(&pe, g_embed);
    cudaGetSymbolAddress(&pz, g_zn);
    cudaGetSymbolAddress(&ps, g_scores);
    float* emb    = (float*)pe;
    float* zn     = (float*)pz;
    float* scores = (float*)ps;

    cudaFuncSetAttribute(tower_kernel,
                         cudaFuncAttributeMaxDynamicSharedMemorySize, TOWER_SMEM_BYTES);

    prep_kernel<<<513, 128>>>(state_e, zv, scale);
    embed_kernel<<<B_, 256>>>(s, sp, cew, ceb);
    wconv_kernel<<<(2 * ESZ_ * 8192 / 4) / 256, 256>>>(p1lw, p2lw);
    tower_kernel<<<dim3(B_, 2), 256, TOWER_SMEM_BYTES>>>(
        p1c1w, p1c1b, p1c2w, p1c2b, p2c1w, p2c1b, p2c2w, p2c2b);

    // both tower linears via HMMA bf16 hi/lo 3-term split
    hmma_linear_kernel<<<dim3(4, 16, 2), 256>>>();

    // bias + normalize -> g_embed (both towers)
    reduce_norm_kernel<<<2 * B_, 128>>>(p1lb, p2lb);

    // scores = embed2 . zn^T
    sgemm_kernel<false, false><<<dim3(4, 16), 256>>>(
        emb + (size_t)B_ * ESZ_, zn, scores, B_, NZ_, ESZ_);

    argmax_kernel<<<B_, 256>>>();

    // out = exp(scale) * embed1 . zn[z_inds]^T
    sgemm_kernel<true, true><<<dim3(16, 16), 256>>>(
        emb, zn, (float*)d_out, B_, B_, ESZ_);
}